// round 1
// baseline (speedup 1.0000x reference)
#include <cuda_runtime.h>
#include <cstdint>

// Problem constants
#define E_  8
#define T_  2048
#define H_  2880
#define D_  2880
#define N2_ 5760   // 2*D

// Tiling
constexpr int BM = 128, BN = 96, BK = 32;
constexpr int LDA = BK + 4;    // 36  (smem A row stride, floats)
constexpr int LDB = BN + 4;    // 100 (smem B row stride)
constexpr int LDC = BN + 4;    // 100 (smem C row stride)
constexpr int AS_SZ = BM * LDA;        // 4608 floats
constexpr int BS_SZ = BK * LDB;        // 3200 floats
constexpr int SMEM_BYTES = (2 * AS_SZ + 2 * BS_SZ) * 4;  // 62464 B (C tile aliases: 51200 B)

// Scratch: routing-scaled activated hidden states, [E][T][D] fp32 (189 MB)
__device__ float g_hidden[(long long)E_ * T_ * D_];

// ---------------- low-level helpers ----------------
__device__ __forceinline__ unsigned smem_u32(const void* p) {
    return (unsigned)__cvta_generic_to_shared(p);
}
__device__ __forceinline__ void cp16(float* s, const float* g) {
    asm volatile("cp.async.cg.shared.global [%0], [%1], 16;" :: "r"(smem_u32(s)), "l"(g));
}
__device__ __forceinline__ void cp_commit() { asm volatile("cp.async.commit_group;"); }
__device__ __forceinline__ void cp_wait1()  { asm volatile("cp.async.wait_group 1;"); }
__device__ __forceinline__ void cp_wait0()  { asm volatile("cp.async.wait_group 0;"); }

__device__ __forceinline__ uint32_t f2tf32(float x) {
    uint32_t r; asm("cvt.rna.tf32.f32 %0, %1;" : "=r"(r) : "f"(x)); return r;
}
__device__ __forceinline__ void mma8(float* c, const uint32_t* a, const uint32_t* b) {
    asm volatile("mma.sync.aligned.m16n8k8.row.col.f32.tf32.tf32.f32 "
        "{%0,%1,%2,%3}, {%4,%5,%6,%7}, {%8,%9}, {%0,%1,%2,%3};"
        : "+f"(c[0]), "+f"(c[1]), "+f"(c[2]), "+f"(c[3])
        : "r"(a[0]), "r"(a[1]), "r"(a[2]), "r"(a[3]), "r"(b[0]), "r"(b[1]));
}

// ---------------- tile loads (cp.async, 16B chunks, no bounds checks: all dims divide) ----
__device__ __forceinline__ void load_A(float* As, const float* Ag, int lda, int tid) {
#pragma unroll
    for (int i = 0; i < 4; i++) {
        int c = tid + i * 256;
        int r = c >> 3, q = (c & 7) << 2;       // 128 rows x 8 chunks
        cp16(As + r * LDA + q, Ag + (long long)r * lda + q);
    }
}
__device__ __forceinline__ void load_B(float* Bs, const float* Bg, int ldb, int tid) {
#pragma unroll
    for (int i = 0; i < 3; i++) {
        int c = tid + i * 256;
        int r = c / 24, q = (c % 24) << 2;      // 32 rows x 24 chunks
        cp16(Bs + r * LDB + q, Bg + (long long)r * ldb + q);
    }
}

// ---------------- per-stage compute: warp tile 32x48, m16n8k8 tf32 ----------------
__device__ __forceinline__ void compute_stage(const float* As, const float* Bs,
                                               float (&acc)[2][6][4],
                                               int wm, int wn, int lane) {
    const int ra = lane >> 2;     // 0..7
    const int ca = lane & 3;      // 0..3
#pragma unroll
    for (int ks = 0; ks < 4; ks++) {
        const int k0 = ks * 8;
        uint32_t a[2][4], b[6][2];
#pragma unroll
        for (int i = 0; i < 2; i++) {
            const float* ap = As + (wm * 32 + i * 16 + ra) * LDA + k0 + ca;
            a[i][0] = f2tf32(ap[0]);
            a[i][1] = f2tf32(ap[8 * LDA]);
            a[i][2] = f2tf32(ap[4]);
            a[i][3] = f2tf32(ap[8 * LDA + 4]);
        }
#pragma unroll
        for (int j = 0; j < 6; j++) {
            const float* bp = Bs + (k0 + ca) * LDB + wn * 48 + j * 8 + ra;
            b[j][0] = f2tf32(bp[0]);
            b[j][1] = f2tf32(bp[4 * LDB]);
        }
#pragma unroll
        for (int i = 0; i < 2; i++)
#pragma unroll
            for (int j = 0; j < 6; j++)
                mma8(acc[i][j], a[i], b[j]);
    }
}

__device__ __forceinline__ void store_acc(float* Cs, const float (&acc)[2][6][4],
                                          int wm, int wn, int lane) {
    const int r0 = lane >> 2, c0 = 2 * (lane & 3);
#pragma unroll
    for (int i = 0; i < 2; i++)
#pragma unroll
        for (int j = 0; j < 6; j++) {
            float* p = Cs + (wm * 32 + i * 16 + r0) * LDC + wn * 48 + j * 8 + c0;
            p[0] = acc[i][j][0];
            p[1] = acc[i][j][1];
            p[8 * LDC]     = acc[i][j][2];
            p[8 * LDC + 1] = acc[i][j][3];
        }
}

// ================= Kernel 1: gate_up GEMM + bias + interleaved GLU + routing scale ====
__global__ void __launch_bounds__(256, 2)
k_gateup(const float* __restrict__ x, const float* __restrict__ w1,
         const float* __restrict__ b1, const float* __restrict__ routing) {
    extern __shared__ float sm[];
    float* Asb[2] = { sm, sm + AS_SZ };
    float* Bsb[2] = { sm + 2 * AS_SZ, sm + 2 * AS_SZ + BS_SZ };
    float* Cs = sm;

    const int tid = threadIdx.x, lane = tid & 31, warp = tid >> 5;
    const int wm = warp & 3, wn = warp >> 2;
    const int n0 = blockIdx.x * BN;           // gate_up column base (even)
    const int t0 = blockIdx.y * BM;
    const int e  = blockIdx.z;

    const float* Abase = x + (long long)t0 * H_;
    const float* Bbase = w1 + (long long)e * H_ * N2_ + n0;

    float acc[2][6][4];
#pragma unroll
    for (int i = 0; i < 2; i++)
#pragma unroll
        for (int j = 0; j < 6; j++)
#pragma unroll
            for (int q = 0; q < 4; q++) acc[i][j][q] = 0.f;

    constexpr int KT = H_ / BK;  // 90
    load_A(Asb[0], Abase, H_, tid);
    load_B(Bsb[0], Bbase, N2_, tid);
    cp_commit();

    for (int kt = 0; kt < KT; kt++) {
        const int nkt = kt + 1;
        if (nkt < KT) {
            load_A(Asb[nkt & 1], Abase + nkt * BK, H_, tid);
            load_B(Bsb[nkt & 1], Bbase + (long long)nkt * BK * N2_, N2_, tid);
            cp_commit();
            cp_wait1();
        } else {
            cp_wait0();
        }
        __syncthreads();
        compute_stage(Asb[kt & 1], Bsb[kt & 1], acc, wm, wn, lane);
        __syncthreads();
    }

    store_acc(Cs, acc, wm, wn, lane);
    __syncthreads();

    // epilogue: bias + interleaved GLU (even=gate, odd=up), scale by routing weight
    const float* brow = b1 + e * N2_ + n0;
    const int j0 = n0 >> 1;
    for (int idx = tid; idx < BM * 48; idx += 256) {
        const int r = idx / 48, m = idx % 48;
        float gate = Cs[r * LDC + 2 * m]     + brow[2 * m];
        float up   = Cs[r * LDC + 2 * m + 1] + brow[2 * m + 1];
        gate = fminf(gate, 7.0f);
        up   = fminf(fmaxf(up, -7.0f), 7.0f);
        const float glu = gate / (1.0f + __expf(-1.702f * gate));
        const float hv  = (up + 1.0f) * glu;
        const int t = t0 + r;
        g_hidden[((long long)e * T_ + t) * D_ + j0 + m] = hv * routing[t * E_ + e];
    }
}

// ================= Kernel 2: flat GEMM over K = E*D, epilogue adds routed down-bias ====
__global__ void __launch_bounds__(256, 2)
k_down(const float* __restrict__ w2, const float* __restrict__ b2,
       const float* __restrict__ routing, float* __restrict__ out) {
    extern __shared__ float sm[];
    float* Asb[2] = { sm, sm + AS_SZ };
    float* Bsb[2] = { sm + 2 * AS_SZ, sm + 2 * AS_SZ + BS_SZ };
    float* Cs = sm;

    const int tid = threadIdx.x, lane = tid & 31, warp = tid >> 5;
    const int wm = warp & 3, wn = warp >> 2;
    const int h0 = blockIdx.x * BN;
    const int t0 = blockIdx.y * BM;

    float acc[2][6][4];
#pragma unroll
    for (int i = 0; i < 2; i++)
#pragma unroll
        for (int j = 0; j < 6; j++)
#pragma unroll
            for (int q = 0; q < 4; q++) acc[i][j][q] = 0.f;

    constexpr int KPE = D_ / BK;        // 90 per expert
    constexpr int KT  = E_ * KPE;       // 720 total

    load_A(Asb[0], g_hidden + (long long)t0 * D_, D_, tid);
    load_B(Bsb[0], w2 + h0, H_, tid);
    cp_commit();

    for (int kt = 0; kt < KT; kt++) {
        const int nkt = kt + 1;
        if (nkt < KT) {
            const int e = nkt / KPE, kk = nkt - e * KPE;
            load_A(Asb[nkt & 1],
                   g_hidden + ((long long)e * T_ + t0) * D_ + kk * BK, D_, tid);
            load_B(Bsb[nkt & 1],
                   w2 + ((long long)e * D_ + kk * BK) * H_ + h0, H_, tid);
            cp_commit();
            cp_wait1();
        } else {
            cp_wait0();
        }
        __syncthreads();
        compute_stage(Asb[kt & 1], Bsb[kt & 1], acc, wm, wn, lane);
        __syncthreads();
    }

    store_acc(Cs, acc, wm, wn, lane);
    __syncthreads();

    for (int idx = tid; idx < BM * BN; idx += 256) {
        const int r = idx / BN, c = idx % BN;
        const int t = t0 + r, h = h0 + c;
        const float* rw = routing + t * E_;
        float bias = 0.f;
#pragma unroll
        for (int e = 0; e < E_; e++) bias += rw[e] * b2[e * H_ + h];
        out[(long long)t * H_ + h] = Cs[r * LDC + c] + bias;
    }
}

// ================= launch ====================
extern "C" void kernel_launch(void* const* d_in, const int* in_sizes, int n_in,
                              void* d_out, int out_size) {
    // Identify inputs by element count (all six are distinct)
    const float *x = nullptr, *rw = nullptr, *w1 = nullptr, *b1 = nullptr,
                *w2 = nullptr, *b2 = nullptr;
    for (int i = 0; i < n_in; i++) {
        const long long s = in_sizes[i];
        const float* p = (const float*)d_in[i];
        if      (s == (long long)T_ * H_)        x  = p;
        else if (s == (long long)T_ * E_)        rw = p;
        else if (s == (long long)E_ * H_ * N2_)  w1 = p;
        else if (s == (long long)E_ * N2_)       b1 = p;
        else if (s == (long long)E_ * D_ * H_)   w2 = p;
        else if (s == (long long)E_ * H_)        b2 = p;
    }
    float* out = (float*)d_out;

    cudaFuncSetAttribute(k_gateup, cudaFuncAttributeMaxDynamicSharedMemorySize, SMEM_BYTES);
    cudaFuncSetAttribute(k_down,   cudaFuncAttributeMaxDynamicSharedMemorySize, SMEM_BYTES);

    dim3 g1(N2_ / BN, T_ / BM, E_);   // 60 x 16 x 8
    k_gateup<<<g1, 256, SMEM_BYTES>>>(x, w1, b1, rw);

    dim3 g2(H_ / BN, T_ / BM);        // 30 x 16
    k_down<<<g2, 256, SMEM_BYTES>>>(w2, b2, rw, out);
}